// round 12
// baseline (speedup 1.0000x reference)
#include <cuda_runtime.h>

#define BN 256
#define CN 1024
#define HW 169        // 13*13
#define SPLIT 4       // -> 1024 accum blocks
#define Z_CONST 17.079468445347132f   // 2*pi*e
#define EPS_CONST 1e-6f

// Per-(b, split, moment, channel) partials: S, Sx, Sy, Sr=Σ(wx^2+wy^2)f. 16.8 MB.
__device__ float g_part[BN * SPLIT * 4 * CN];
__device__ float g_bsum[BN];
__device__ unsigned g_bcnt[BN];   // zero-init at load; self-resetting per replay
__device__ unsigned g_allcnt;     // zero-init at load; self-resetting per replay

// packed fp32x2 ops (PTX-only; ptxas won't auto-fuse)
#define PACK2(d, lo, hi)   asm("mov.b64 %0, {%1, %2};" : "=l"(d) : "f"(lo), "f"(hi))
#define FMA2(d, a, b, c)   asm("fma.rn.f32x2 %0, %1, %2, %3;" : "=l"(d) : "l"(a), "l"(b), "l"(c))

// ---------------------------------------------------------------------------
// Single fused kernel. Main loop identical to R10 winner (4 positions per
// barrier). Epilogue: last-finisher-per-batch reduces that batch's partials
// (L2-hot) to g_bsum[b]; overall last batch-finisher reduces g_bsum -> out.
// ---------------------------------------------------------------------------
__global__ __launch_bounds__(256, 3) void accum_kernel(const float* __restrict__ x,
                                                       float* __restrict__ out) {
    const int b    = blockIdx.x >> 2;
    const int sp   = blockIdx.x & 3;
    const int p0   = (sp * HW) >> 2;           // 0,42,84,126
    const int p1   = ((sp + 1) * HW) >> 2;     // 42,84,126,169
    const int tid  = threadIdx.x;
    const int wid  = tid >> 5;
    const int lane = tid & 31;

    __shared__ __align__(16) float red[2][4][8];   // [buf][pos-in-group][warp]
    __shared__ unsigned flag;

    const float4* __restrict__ xb = (const float4*)(x + (size_t)b * HW * CN) + tid;

    unsigned long long S[2]  = {0, 0};
    unsigned long long Sx[2] = {0, 0};
    unsigned long long Sy[2] = {0, 0};
    unsigned long long Sr[2] = {0, 0};

    const int n       = p1 - p0;
    const int ngroups = (n + 3) >> 2;

    // prologue: load group 0 (clamped)
    float4 buf[4];
#pragma unroll
    for (int j = 0; j < 4; ++j) {
        int p = p0 + j; if (p >= p1) p = p1 - 1;
        buf[j] = __ldcs(xb + (size_t)p * 256);
    }

    for (int g = 0; g < ngroups; ++g) {
        const int pbase = p0 + 4 * g;

        // ---- exps for 4 positions ----
        float e[16];
#pragma unroll
        for (int j = 0; j < 4; ++j) {
            e[4 * j + 0] = __expf(buf[j].x);
            e[4 * j + 1] = __expf(buf[j].y);
            e[4 * j + 2] = __expf(buf[j].z);
            e[4 * j + 3] = __expf(buf[j].w);
        }

        // ---- prefetch group g+1 (WAR overwrite) ----
        if (g + 1 < ngroups) {
#pragma unroll
            for (int j = 0; j < 4; ++j) {
                int p = pbase + 4 + j; if (p >= p1) p = p1 - 1;
                buf[j] = __ldcs(xb + (size_t)p * 256);
            }
        }

        // ---- 4 interleaved warp-reduction chains ----
        float s0 = (e[0]  + e[1])  + (e[2]  + e[3]);
        float s1 = (e[4]  + e[5])  + (e[6]  + e[7]);
        float s2 = (e[8]  + e[9])  + (e[10] + e[11]);
        float s3 = (e[12] + e[13]) + (e[14] + e[15]);
#pragma unroll
        for (int m = 16; m > 0; m >>= 1) {
            s0 += __shfl_xor_sync(0xffffffffu, s0, m);
            s1 += __shfl_xor_sync(0xffffffffu, s1, m);
            s2 += __shfl_xor_sync(0xffffffffu, s2, m);
            s3 += __shfl_xor_sync(0xffffffffu, s3, m);
        }
        if (lane == 0) {
            red[g & 1][0][wid] = s0;
            red[g & 1][1][wid] = s1;
            red[g & 1][2][wid] = s2;
            red[g & 1][3][wid] = s3;
        }
        __syncthreads();

        // ---- denominators + accumulate 4 positions ----
#pragma unroll
        for (int j = 0; j < 4; ++j) {
            const float4* rp = (const float4*)red[g & 1][j];
            float4 ra = rp[0], rb = rp[1];
            float den = ((ra.x + ra.y) + (ra.z + ra.w))
                      + ((rb.x + rb.y) + (rb.z + rb.w));
            const int p = pbase + j;
            float inv = (p < p1) ? __fdividef(1.0f, den) : 0.0f;
            const unsigned pc = (p < p1) ? (unsigned)p : 0u;
            const unsigned h  = (pc * 5042u) >> 16;         // floor(p/13), p<169
            float wxj = (float)(h + 1);
            float wyj = (float)(pc - h * 13u + 1u);
            float w1  = inv * wxj;
            float w2  = inv * wyj;
            float wr  = fmaf(wxj, wxj, wyj * wyj) * inv;

            unsigned long long ea, eb, inv2, w12, w22, wr2;
            PACK2(ea, e[4 * j + 0], e[4 * j + 1]);
            PACK2(eb, e[4 * j + 2], e[4 * j + 3]);
            PACK2(inv2, inv, inv); PACK2(w12, w1, w1);
            PACK2(w22, w2, w2);    PACK2(wr2, wr, wr);

            FMA2(S[0],  inv2, ea, S[0]);  FMA2(S[1],  inv2, eb, S[1]);
            FMA2(Sx[0], w12,  ea, Sx[0]); FMA2(Sx[1], w12,  eb, Sx[1]);
            FMA2(Sy[0], w22,  ea, Sy[0]); FMA2(Sy[1], w22,  eb, Sy[1]);
            FMA2(Sr[0], wr2,  ea, Sr[0]); FMA2(Sr[1], wr2,  eb, Sr[1]);
        }
    }

    // ---- store partials: [B][SPLIT][4][CN] ----
    float* gp = g_part + (size_t)(b * SPLIT + sp) * 4 * CN;
    const int c4 = tid << 2;
    *(ulonglong2*)(gp + 0 * CN + c4) = make_ulonglong2(S[0],  S[1]);
    *(ulonglong2*)(gp + 1 * CN + c4) = make_ulonglong2(Sx[0], Sx[1]);
    *(ulonglong2*)(gp + 2 * CN + c4) = make_ulonglong2(Sy[0], Sy[1]);
    *(ulonglong2*)(gp + 3 * CN + c4) = make_ulonglong2(Sr[0], Sr[1]);

    // ---- last-finisher-per-batch epilogue (threadFenceReduction pattern) ----
    __threadfence();                 // all threads: make my stores visible
    __syncthreads();                 // all stores of this block precede the atomic
    if (tid == 0)
        flag = (atomicAdd(&g_bcnt[b], 1u) == SPLIT - 1) ? 1u : 0u;
    __syncthreads();
    if (!flag) return;

    if (tid == 0) g_bcnt[b] = 0;     // reset for next graph replay
    __threadfence();                 // acquire: sibling partials now visible

    // reduce this batch: 4 channels/thread, 16 float4 loads (L2-hot)
    float m0[4] = {0,0,0,0}, m1[4] = {0,0,0,0}, m2[4] = {0,0,0,0}, m3[4] = {0,0,0,0};
#pragma unroll
    for (int s = 0; s < SPLIT; ++s) {
        const float* gs = g_part + (size_t)(b * SPLIT + s) * 4 * CN;
        float4 a0 = *(const float4*)(gs + 0 * CN + c4);
        float4 a1 = *(const float4*)(gs + 1 * CN + c4);
        float4 a2 = *(const float4*)(gs + 2 * CN + c4);
        float4 a3 = *(const float4*)(gs + 3 * CN + c4);
        m0[0] += a0.x; m0[1] += a0.y; m0[2] += a0.z; m0[3] += a0.w;
        m1[0] += a1.x; m1[1] += a1.y; m1[2] += a1.z; m1[3] += a1.w;
        m2[0] += a2.x; m2[1] += a2.y; m2[2] += a2.z; m2[3] += a2.w;
        m3[0] += a3.x; m3[1] += a3.y; m3[2] += a3.z; m3[3] += a3.w;
    }

    float acc = 0.0f;
#pragma unroll
    for (int j = 0; j < 4; ++j) {
        float s     = m0[j] + EPS_CONST;
        float inv_s = 1.0f / s;
        float mx    = m1[j] * inv_s;
        float my    = m2[j] * inv_s;
        float num   = m3[j] - 2.0f * (mx * m1[j] + my * m2[j])
                    + (mx * mx + my * my) * m0[j];
        float d     = num * inv_s * (1.0f / 169.0f);
        acc = fmaf(d * d, Z_CONST, acc);
    }
#pragma unroll
    for (int msk = 16; msk > 0; msk >>= 1)
        acc += __shfl_xor_sync(0xffffffffu, acc, msk);

    __shared__ float wsum[8];
    if (lane == 0) wsum[wid] = acc;
    __syncthreads();

    // publish per-batch sum; detect overall-last batch
    if (tid == 0) {
        g_bsum[b] = ((wsum[0] + wsum[1]) + (wsum[2] + wsum[3]))
                  + ((wsum[4] + wsum[5]) + (wsum[6] + wsum[7]));
        __threadfence();
        flag = (atomicAdd(&g_allcnt, 1u) == BN - 1) ? 1u : 0u;
    }
    __syncthreads();
    if (!flag) return;

    if (tid == 0) g_allcnt = 0;      // reset for next graph replay
    __threadfence();                 // acquire: all g_bsum visible

    // final reduction of 256 batch sums (blockDim == BN)
    float v = g_bsum[tid];
#pragma unroll
    for (int msk = 16; msk > 0; msk >>= 1)
        v += __shfl_xor_sync(0xffffffffu, v, msk);
    if (lane == 0) wsum[wid] = v;
    __syncthreads();
    if (tid == 0) {
        float t = ((wsum[0] + wsum[1]) + (wsum[2] + wsum[3]))
                + ((wsum[4] + wsum[5]) + (wsum[6] + wsum[7]));
        out[0] = t * (1.0f / (float)(BN * CN));
    }
}

// ---------------------------------------------------------------------------
extern "C" void kernel_launch(void* const* d_in, const int* in_sizes, int n_in,
                              void* d_out, int out_size) {
    const float* x = (const float*)d_in[0];
    float* out = (float*)d_out;

    accum_kernel<<<BN * SPLIT, 256>>>(x, out);
}

// round 13
// speedup vs baseline: 1.4490x; 1.4490x over previous
#include <cuda_runtime.h>

#define BN 256
#define CN 1024
#define HW 169        // 13*13
#define SPLIT 2       // -> 512 accum blocks = ONE wave at 4 blocks/SM
#define Z_CONST 17.079468445347132f   // 2*pi*e
#define EPS_CONST 1e-6f

// Per-(b, split, moment, channel) partials: S, Sx, Sy, Sr=Σ(wx^2+wy^2)f. 8.4 MB.
__device__ float g_part[BN * SPLIT * 4 * CN];

// packed fp32x2 ops (PTX-only; ptxas won't auto-fuse)
#define PACK2(d, lo, hi)   asm("mov.b64 %0, {%1, %2};" : "=l"(d) : "f"(lo), "f"(hi))
#define FMA2(d, a, b, c)   asm("fma.rn.f32x2 %0, %1, %2, %3;" : "=l"(d) : "l"(a), "l"(b), "l"(c))

// ---------------------------------------------------------------------------
// Kernel 1 (R10 winner loop, SPLIT=2): 256 thr/block, thread owns channels
// [4t,4t+4). FOUR positions per barrier: 16 exps, 4 interleaved shfl chains,
// one __syncthreads, 4 denominators + 32 FMA2. Group-level prefetch (MLP=4).
// ---------------------------------------------------------------------------
__global__ __launch_bounds__(256, 4) void accum_kernel(const float* __restrict__ x,
                                                       float* __restrict__ out) {
    if (blockIdx.x == 0 && threadIdx.x == 0) out[0] = 0.0f;

    const int b    = blockIdx.x >> 1;
    const int sp   = blockIdx.x & 1;
    const int p0   = sp ? 85 : 0;
    const int p1   = sp ? HW : 85;
    const int tid  = threadIdx.x;
    const int wid  = tid >> 5;
    const int lane = tid & 31;

    __shared__ __align__(16) float red[2][4][8];   // [buf][pos-in-group][warp]

    const float4* __restrict__ xb = (const float4*)(x + (size_t)b * HW * CN) + tid;

    unsigned long long S[2]  = {0, 0};
    unsigned long long Sx[2] = {0, 0};
    unsigned long long Sy[2] = {0, 0};
    unsigned long long Sr[2] = {0, 0};

    const int n       = p1 - p0;
    const int ngroups = (n + 3) >> 2;              // 22 / 21

    // prologue: load group 0 (clamped)
    float4 buf[4];
#pragma unroll
    for (int j = 0; j < 4; ++j) {
        int p = p0 + j; if (p >= p1) p = p1 - 1;
        buf[j] = __ldcs(xb + (size_t)p * 256);
    }

    for (int g = 0; g < ngroups; ++g) {
        const int pbase = p0 + 4 * g;

        // ---- exps for 4 positions (consume bufs) ----
        float e[16];
#pragma unroll
        for (int j = 0; j < 4; ++j) {
            e[4 * j + 0] = __expf(buf[j].x);
            e[4 * j + 1] = __expf(buf[j].y);
            e[4 * j + 2] = __expf(buf[j].z);
            e[4 * j + 3] = __expf(buf[j].w);
        }

        // ---- prefetch group g+1 (WAR overwrite) ----
        if (g + 1 < ngroups) {
#pragma unroll
            for (int j = 0; j < 4; ++j) {
                int p = pbase + 4 + j; if (p >= p1) p = p1 - 1;
                buf[j] = __ldcs(xb + (size_t)p * 256);
            }
        }

        // ---- 4 interleaved warp-reduction chains ----
        float s0 = (e[0]  + e[1])  + (e[2]  + e[3]);
        float s1 = (e[4]  + e[5])  + (e[6]  + e[7]);
        float s2 = (e[8]  + e[9])  + (e[10] + e[11]);
        float s3 = (e[12] + e[13]) + (e[14] + e[15]);
#pragma unroll
        for (int m = 16; m > 0; m >>= 1) {
            s0 += __shfl_xor_sync(0xffffffffu, s0, m);
            s1 += __shfl_xor_sync(0xffffffffu, s1, m);
            s2 += __shfl_xor_sync(0xffffffffu, s2, m);
            s3 += __shfl_xor_sync(0xffffffffu, s3, m);
        }
        if (lane == 0) {
            red[g & 1][0][wid] = s0;
            red[g & 1][1][wid] = s1;
            red[g & 1][2][wid] = s2;
            red[g & 1][3][wid] = s3;
        }
        __syncthreads();

        // ---- denominators + accumulate 4 positions ----
#pragma unroll
        for (int j = 0; j < 4; ++j) {
            const float4* rp = (const float4*)red[g & 1][j];
            float4 ra = rp[0], rb = rp[1];
            float den = ((ra.x + ra.y) + (ra.z + ra.w))
                      + ((rb.x + rb.y) + (rb.z + rb.w));
            const int p = pbase + j;
            float inv = (p < p1) ? __fdividef(1.0f, den) : 0.0f;
            const unsigned pc = (p < p1) ? (unsigned)p : 0u;
            const unsigned h  = (pc * 5042u) >> 16;         // floor(p/13), p<169
            float wxj = (float)(h + 1);
            float wyj = (float)(pc - h * 13u + 1u);
            float w1  = inv * wxj;
            float w2  = inv * wyj;
            float wr  = fmaf(wxj, wxj, wyj * wyj) * inv;

            unsigned long long ea, eb, inv2, w12, w22, wr2;
            PACK2(ea, e[4 * j + 0], e[4 * j + 1]);
            PACK2(eb, e[4 * j + 2], e[4 * j + 3]);
            PACK2(inv2, inv, inv); PACK2(w12, w1, w1);
            PACK2(w22, w2, w2);    PACK2(wr2, wr, wr);

            FMA2(S[0],  inv2, ea, S[0]);  FMA2(S[1],  inv2, eb, S[1]);
            FMA2(Sx[0], w12,  ea, Sx[0]); FMA2(Sx[1], w12,  eb, Sx[1]);
            FMA2(Sy[0], w22,  ea, Sy[0]); FMA2(Sy[1], w22,  eb, Sy[1]);
            FMA2(Sr[0], wr2,  ea, Sr[0]); FMA2(Sr[1], wr2,  eb, Sr[1]);
        }
    }

    // ---- coalesced partial stores: [B][SPLIT][4][CN] ----
    float* gp = g_part + (size_t)(b * SPLIT + sp) * 4 * CN;
    const int c4 = tid << 2;
    *(ulonglong2*)(gp + 0 * CN + c4) = make_ulonglong2(S[0],  S[1]);
    *(ulonglong2*)(gp + 1 * CN + c4) = make_ulonglong2(Sx[0], Sx[1]);
    *(ulonglong2*)(gp + 2 * CN + c4) = make_ulonglong2(Sy[0], Sy[1]);
    *(ulonglong2*)(gp + 3 * CN + c4) = make_ulonglong2(Sr[0], Sr[1]);
}

// ---------------------------------------------------------------------------
// Kernel 2: sum splits, per-(b,c) det, block reduce, one atomic per block.
// 1024 blocks x 256 thr; thread owns ONE channel (fully coalesced; 8 loads).
// ---------------------------------------------------------------------------
__global__ __launch_bounds__(256) void final_kernel(float* __restrict__ out) {
    const int bb  = blockIdx.x;          // 0..1023: 4 blocks per batch
    const int b   = bb >> 2;
    const int c   = ((bb & 3) << 8) + threadIdx.x;
    const int tid = threadIdx.x;

    const float* g0 = g_part + (size_t)(b * SPLIT + 0) * 4 * CN;
    const float* g1 = g_part + (size_t)(b * SPLIT + 1) * 4 * CN;

    float m0 = g0[0 * CN + c] + g1[0 * CN + c];
    float m1 = g0[1 * CN + c] + g1[1 * CN + c];
    float m2 = g0[2 * CN + c] + g1[2 * CN + c];
    float m3 = g0[3 * CN + c] + g1[3 * CN + c];

    float s     = m0 + EPS_CONST;
    float inv_s = 1.0f / s;
    float mx    = m1 * inv_s;
    float my    = m2 * inv_s;
    float num   = m3 - 2.0f * (mx * m1 + my * m2) + (mx * mx + my * my) * m0;
    float d     = num * inv_s * (1.0f / 169.0f);
    float acc   = d * d * Z_CONST;

#pragma unroll
    for (int msk = 16; msk > 0; msk >>= 1)
        acc += __shfl_xor_sync(0xffffffffu, acc, msk);

    __shared__ float wsum[8];
    if ((tid & 31) == 0) wsum[tid >> 5] = acc;
    __syncthreads();
    if (tid == 0) {
        float t = ((wsum[0] + wsum[1]) + (wsum[2] + wsum[3]))
                + ((wsum[4] + wsum[5]) + (wsum[6] + wsum[7]));
        atomicAdd(out, t * (1.0f / (float)(BN * CN)));
    }
}

// ---------------------------------------------------------------------------
extern "C" void kernel_launch(void* const* d_in, const int* in_sizes, int n_in,
                              void* d_out, int out_size) {
    const float* x = (const float*)d_in[0];
    float* out = (float*)d_out;

    accum_kernel<<<BN * SPLIT, 256>>>(x, out);
    final_kernel<<<1024, 256>>>(out);
}